// round 16
// baseline (speedup 1.0000x reference)
#include <cuda_runtime.h>
#include <cuda_fp16.h>
#include <cstdint>

// Problem shape (fixed)
#define BB 16
#define CC 512
#define LL 4096

typedef __half hf;

// ---------------- Scratch (device globals; no allocation allowed) -----------
__device__ __align__(256) hf g_xh[(size_t)BB * CC * LL];
__device__ __align__(256) hf g_vh[(size_t)BB * CC * LL];
__device__ __align__(256) hf g_kh[(size_t)BB * CC * LL];   // logits, then softmax in-place
__device__ __align__(256) hf g_ch[(size_t)BB * CC * CC];
__device__ __align__(256) hf g_mh[(size_t)BB * CC * CC];
__device__ __align__(256) hf g_mwh[(size_t)BB * CC * CC];  // MW = M @ Wq
__device__ __align__(256) hf g_wqh[3 * CC * CC];
__device__ __align__(256) hf g_woh[CC * CC];

// ---------------- PTX helpers ----------------
__device__ __forceinline__ uint32_t smem_u32(const void* p) {
    uint32_t a;
    asm("{ .reg .u64 t; cvta.to.shared.u64 t, %1; cvt.u32.u64 %0, t; }" : "=r"(a) : "l"(p));
    return a;
}
#define LDSM4(r0, r1, r2, r3, addr) \
    asm volatile("ldmatrix.sync.aligned.m8n8.x4.shared.b16 {%0,%1,%2,%3}, [%4];" \
                 : "=r"(r0), "=r"(r1), "=r"(r2), "=r"(r3) : "r"(addr))
#define LDSM4T(r0, r1, r2, r3, addr) \
    asm volatile("ldmatrix.sync.aligned.m8n8.x4.trans.shared.b16 {%0,%1,%2,%3}, [%4];" \
                 : "=r"(r0), "=r"(r1), "=r"(r2), "=r"(r3) : "r"(addr))
#define MMA16816(c, a, b) \
    asm volatile("mma.sync.aligned.m16n8k16.row.col.f32.f16.f16.f32 " \
                 "{%0,%1,%2,%3}, {%4,%5,%6,%7}, {%8,%9}, {%0,%1,%2,%3};" \
                 : "+f"((c)[0]), "+f"((c)[1]), "+f"((c)[2]), "+f"((c)[3]) \
                 : "r"((a)[0]), "r"((a)[1]), "r"((a)[2]), "r"((a)[3]), \
                   "r"((b)[0]), "r"((b)[1]))
#define CP16(dst, src) \
    asm volatile("cp.async.cg.shared.global [%0], [%1], 16;" :: "r"(dst), "l"(src))
#define CP_COMMIT() asm volatile("cp.async.commit_group;" ::: "memory")
#define CP_WAIT(n)  asm volatile("cp.async.wait_group %0;" :: "n"(n) : "memory")

__device__ __forceinline__ uint32_t pack2h(float f0, float f1) {
    __half2 h = __float22half2_rn(make_float2(f0, f1));
    return *reinterpret_cast<uint32_t*>(&h);
}

// ============================================================================
// wgemm: C[m,n] = sum_k A[m,k] * B'[k,n], fp16 1-pass HMMA.
//   B_IS_KN=true : B stored [K,N] (NN);  false: [N,K] (NT)
//   EPI: 0 = fp32 out (+bias), 2 = GEMM1 2-way fp16 (half 0->C0 k-logits,
//        half 1->C1 v), 3 = fp16 out (C0).
// Block tile 128x128, K-chunk 64, 3-stage cp.async ring (32KB stages),
// 128 thr (4 warps 2x2, warp tile 64x64), 2 CTAs/SM.
// ============================================================================
#define NSTAGE 3
#define STG_B  32768
#define WG_SMEM (NSTAGE * STG_B)   // 96 KB
#define P_BH 16384

template <bool B_IS_KN, int EPI, bool ADD_BIAS>
__global__ __launch_bounds__(128, 2) void wgemm(
    const hf* __restrict__ Ah, const hf* __restrict__ Bh,
    float* __restrict__ Cf, hf* __restrict__ C0, hf* __restrict__ C1,
    const float* __restrict__ bias,
    int K, long sA, long sB, long sC, int lda, int ldb, int ldc)
{
    extern __shared__ char smem[];
    const uint32_t sb = smem_u32(smem);

    const int tid  = threadIdx.x;
    const int lane = tid & 31;
    const int wid  = tid >> 5;          // 0..3
    const int wm   = wid >> 1;          // 0..1
    const int wn   = wid & 1;           // 0..1
    const int m0 = blockIdx.y * 128;
    const int n0 = blockIdx.x * 128;
    const long z = blockIdx.z;

    Ah += z * sA + (long)m0 * lda;
    Bh += z * sB + (B_IS_KN ? (long)n0 : (long)n0 * ldb);
    if (EPI == 0) Cf += z * sC;
    if (EPI == 2) { C0 += z * sC; C1 += z * sC; }
    if (EPI == 3) C0 += z * sC;

    const int ln15 = lane & 15;
    const int grp  = lane >> 4;
    const int sw8  = ln15 & 7;          // 128B-row swizzle key (per-lane)

    float acc[4][8][4];
    #pragma unroll
    for (int i = 0; i < 4; i++)
        #pragma unroll
        for (int j = 0; j < 8; j++)
            #pragma unroll
            for (int q = 0; q < 4; q++) acc[i][j][q] = 0.0f;

    // -------- cp.async stage fill (K-chunk 64) --------
    auto issue = [&](int chunk, int s) {
        const int k0 = chunk * 64;
        const uint32_t st = sb + s * STG_B;
        #pragma unroll
        for (int i = 0; i < 8; i++) {
            const int seg = tid + i * 128;
            const int row = seg >> 3;
            const int c   = seg & 7;
            const uint32_t doff = row * 128 + (((c ^ (row & 7)) & 7) << 4);
            CP16(st + doff, Ah + (long)row * lda + k0 + c * 8);
        }
        if (!B_IS_KN) {
            #pragma unroll
            for (int i = 0; i < 8; i++) {
                const int seg = tid + i * 128;
                const int row = seg >> 3;
                const int c   = seg & 7;
                const uint32_t doff = row * 128 + (((c ^ (row & 7)) & 7) << 4);
                CP16(st + P_BH + doff, Bh + (long)row * ldb + k0 + c * 8);
            }
        } else {
            // B plane: 64 k-rows x 256B, swizzle cc ^ (k&7)
            #pragma unroll
            for (int i = 0; i < 8; i++) {
                const int seg = tid + i * 128;
                const int k   = seg >> 4;
                const int cc  = seg & 15;
                const uint32_t doff = k * 256 + (((cc ^ (k & 7)) & 15) << 4);
                CP16(st + P_BH + doff, Bh + (long)(k0 + k) * ldb + cc * 8);
            }
        }
    };

    // -------- fragment loads --------
    int a_row_off[4];
    #pragma unroll
    for (int i = 0; i < 4; i++)
        a_row_off[i] = (wm * 64 + i * 16 + ln15) * 128;
    int b_row_off[4];
    #pragma unroll
    for (int jp = 0; jp < 4; jp++)
        b_row_off[jp] = (wn * 64 + jp * 16 + ln15) * 128;

    auto lda_frags = [&](uint32_t plane, int ks, uint32_t af[4][4]) {
        const int c = ks * 2 + grp;     // 0..7
        #pragma unroll
        for (int i = 0; i < 4; i++) {
            uint32_t addr = plane + a_row_off[i] + (((c ^ sw8) & 7) << 4);
            LDSM4(af[i][0], af[i][1], af[i][2], af[i][3], addr);
        }
    };
    auto ldb_frags = [&](uint32_t plane, int ks, uint32_t bf[8][2]) {
        if (B_IS_KN) {
            const uint32_t krow = (uint32_t)(ks * 16 + ln15) << 8;
            #pragma unroll
            for (int jp = 0; jp < 4; jp++) {
                const int cn = wn * 8 + jp * 2 + grp;
                uint32_t addr = plane + krow + (((cn ^ sw8) & 15) << 4);
                uint32_t r0, r1, r2, r3;
                LDSM4T(r0, r1, r2, r3, addr);
                bf[jp * 2    ][0] = r0; bf[jp * 2    ][1] = r1;
                bf[jp * 2 + 1][0] = r2; bf[jp * 2 + 1][1] = r3;
            }
        } else {
            const int c = ks * 2 + grp;
            #pragma unroll
            for (int jp = 0; jp < 4; jp++) {
                uint32_t addr = plane + b_row_off[jp] + (((c ^ sw8) & 7) << 4);
                uint32_t r0, r1, r2, r3;
                LDSM4(r0, r1, r2, r3, addr);
                bf[jp * 2    ][0] = r0; bf[jp * 2    ][1] = r2;
                bf[jp * 2 + 1][0] = r1; bf[jp * 2 + 1][1] = r3;
            }
        }
    };
    auto compute_chunk = [&](int s) {
        const uint32_t base = sb + s * STG_B;
        #pragma unroll
        for (int ks = 0; ks < 4; ks++) {
            uint32_t ah[4][4], bh[8][2];
            lda_frags(base, ks, ah);
            ldb_frags(base + P_BH, ks, bh);
            #pragma unroll
            for (int i = 0; i < 4; i++)
                #pragma unroll
                for (int j = 0; j < 8; j++)
                    MMA16816(acc[i][j], ah[i], bh[j]);
        }
    };

    // -------- multistage main loop (3-stage ring, mod-3 indexing) --------
    const int NC = K >> 6;
    issue(0, 0); CP_COMMIT();
    if (1 < NC) { issue(1, 1); } CP_COMMIT();
    int cur = 0, pfs = 2;
    for (int c = 0; c < NC; c++) {
        CP_WAIT(1);
        __syncthreads();
        const int pf = c + 2;
        if (pf < NC) { issue(pf, pfs); }
        CP_COMMIT();
        compute_chunk(cur);
        if (++cur == NSTAGE) cur = 0;
        if (++pfs == NSTAGE) pfs = 0;
    }

    // -------- epilogue --------
    #pragma unroll
    for (int i = 0; i < 4; i++) {
        const int row = m0 + wm * 64 + i * 16 + (lane >> 2);
        #pragma unroll
        for (int j = 0; j < 8; j++) {
            const int col = n0 + wn * 64 + j * 8 + (lane & 3) * 2;
            if (EPI == 0) {
                float bv0 = 0.0f, bv1 = 0.0f;
                if (ADD_BIAS) { bv0 = bias[row]; bv1 = bias[row + 8]; }
                float2 v0 = make_float2(acc[i][j][0] + bv0, acc[i][j][1] + bv0);
                float2 v1 = make_float2(acc[i][j][2] + bv1, acc[i][j][3] + bv1);
                *reinterpret_cast<float2*>(&Cf[(long)row * ldc + col])       = v0;
                *reinterpret_cast<float2*>(&Cf[(long)(row + 8) * ldc + col]) = v1;
            } else if (EPI == 3) {
                *reinterpret_cast<uint32_t*>(&C0[(long)row * ldc + col]) =
                    pack2h(acc[i][j][0], acc[i][j][1]);
                *reinterpret_cast<uint32_t*>(&C0[(long)(row + 8) * ldc + col]) =
                    pack2h(acc[i][j][2], acc[i][j][3]);
            } else {
                const int half = blockIdx.y >> 2;   // 4 m-tiles of 128 per 512 rows
                const int lr = row & 511;
                hf* d = (half == 0) ? C0 : C1;
                *reinterpret_cast<uint32_t*>(&d[(long)lr * ldc + col]) =
                    pack2h(acc[i][j][0], acc[i][j][1]);
                *reinterpret_cast<uint32_t*>(&d[(long)(lr + 8) * ldc + col]) =
                    pack2h(acc[i][j][2], acc[i][j][3]);
            }
        }
    }
}

// ============================================================================
// split kernel: fp32 -> half
// ============================================================================
__global__ __launch_bounds__(256) void split_hi(
    const float* __restrict__ s, hf* __restrict__ h, long n)
{
    long i = ((long)blockIdx.x * 256 + threadIdx.x) * 4;
    if (i >= n) return;
    float4 v = *reinterpret_cast<const float4*>(s + i);
    *reinterpret_cast<uint2*>(h + i) = make_uint2(pack2h(v.x, v.y), pack2h(v.z, v.w));
}

// ============================================================================
// softmax over L, in-place on fp16 logits (block owns one full row)
// ============================================================================
__global__ __launch_bounds__(256) void softmax_h(hf* __restrict__ kh)
{
    const int r = blockIdx.x;
    const int b = blockIdx.y;
    const long off = ((long)b * CC + r) * LL;
    hf* p = kh + off;
    const int tid = threadIdx.x;
    __shared__ float red[8];

    float v[16];
    float mx = -1e30f;
    #pragma unroll
    for (int i = 0; i < 16; i++) { v[i] = __half2float(p[tid + i * 256]); mx = fmaxf(mx, v[i]); }
    #pragma unroll
    for (int o = 16; o > 0; o >>= 1) mx = fmaxf(mx, __shfl_xor_sync(0xffffffffu, mx, o));
    if ((tid & 31) == 0) red[tid >> 5] = mx;
    __syncthreads();
    if (tid < 32) {
        float m2 = (tid < 8) ? red[tid] : -1e30f;
        #pragma unroll
        for (int o = 4; o > 0; o >>= 1) m2 = fmaxf(m2, __shfl_xor_sync(0xffffffffu, m2, o));
        if (tid == 0) red[0] = m2;
    }
    __syncthreads();
    mx = red[0];
    __syncthreads();

    float s = 0.0f;
    #pragma unroll
    for (int i = 0; i < 16; i++) { v[i] = __expf(v[i] - mx); s += v[i]; }
    #pragma unroll
    for (int o = 16; o > 0; o >>= 1) s += __shfl_xor_sync(0xffffffffu, s, o);
    if ((tid & 31) == 0) red[tid >> 5] = s;
    __syncthreads();
    if (tid < 32) {
        float s2 = (tid < 8) ? red[tid] : 0.0f;
        #pragma unroll
        for (int o = 4; o > 0; o >>= 1) s2 += __shfl_xor_sync(0xffffffffu, s2, o);
        if (tid == 0) red[0] = s2;
    }
    __syncthreads();
    const float inv = 1.0f / red[0];

    #pragma unroll
    for (int i = 0; i < 16; i++)
        p[tid + i * 256] = __float2half_rn(v[i] * inv);
}

// ============================================================================
extern "C" void kernel_launch(void* const* d_in, const int* in_sizes, int n_in,
                              void* d_out, int out_size)
{
    const float* x = nullptr; const float* w_qkv = nullptr;
    const float* w_out = nullptr; const float* b_out = nullptr;
    for (int i = 0; i < n_in; i++) {
        switch (in_sizes[i]) {
            case 33554432: x     = (const float*)d_in[i]; break;
            case 786432:   w_qkv = (const float*)d_in[i]; break;
            case 262144:   w_out = (const float*)d_in[i]; break;
            case 512:      b_out = (const float*)d_in[i]; break;
            default: break;
        }
    }
    float* y = (float*)d_out;

    hf *xh, *vh, *kh, *ch, *mh, *mwh, *wqh, *woh;
    cudaGetSymbolAddress((void**)&xh, g_xh);
    cudaGetSymbolAddress((void**)&vh, g_vh);
    cudaGetSymbolAddress((void**)&kh, g_kh);
    cudaGetSymbolAddress((void**)&ch, g_ch);
    cudaGetSymbolAddress((void**)&mh, g_mh);
    cudaGetSymbolAddress((void**)&mwh, g_mwh);
    cudaGetSymbolAddress((void**)&wqh, g_wqh);
    cudaGetSymbolAddress((void**)&woh, g_woh);

    cudaFuncSetAttribute(wgemm<true,  2, false>, cudaFuncAttributeMaxDynamicSharedMemorySize, WG_SMEM);
    cudaFuncSetAttribute(wgemm<false, 3, false>, cudaFuncAttributeMaxDynamicSharedMemorySize, WG_SMEM);
    cudaFuncSetAttribute(wgemm<true,  3, false>, cudaFuncAttributeMaxDynamicSharedMemorySize, WG_SMEM);
    cudaFuncSetAttribute(wgemm<true,  0, true >, cudaFuncAttributeMaxDynamicSharedMemorySize, WG_SMEM);

    const long sBig = (long)CC * LL;
    const long sCtx = (long)CC * CC;

    // 0) pre-split inputs to fp16
    split_hi<<<(unsigned)((size_t)BB * CC * LL / 1024), 256>>>(x, xh, (long)BB * CC * LL);
    split_hi<<<3 * CC * CC / 1024, 256>>>(w_qkv, wqh, 3 * CC * CC);
    split_hi<<<CC * CC / 1024, 256>>>(w_out, woh, CC * CC);

    // 1) [k;v] = w_qkv[512:1536] @ x (NN): k-logits -> kh, v -> vh
    wgemm<true, 2, false><<<dim3(LL / 128, (2 * CC) / 128, BB), 128, WG_SMEM>>>(
        wqh + (long)CC * CC, xh, nullptr, kh, vh, nullptr,
        CC, 0, sBig, sBig, CC, LL, LL);

    // 2) softmax over L, in-place on kh
    softmax_h<<<dim3(CC, BB), 256>>>(kh);

    // 3) ctx = k_sm @ v^T (NT) -> fp16
    wgemm<false, 3, false><<<dim3(CC / 128, CC / 128, BB), 128, WG_SMEM>>>(
        kh, vh, nullptr, ch, nullptr, nullptr,
        LL, sBig, sBig, sCtx, LL, LL, CC);

    // 4) M = w_out @ ctx^T (NT) -> fp16
    wgemm<false, 3, false><<<dim3(CC / 128, CC / 128, BB), 128, WG_SMEM>>>(
        woh, ch, nullptr, mh, nullptr, nullptr,
        CC, 0, sCtx, sCtx, CC, CC, CC);

    // 4b) MW = M @ Wq (NN, Wq = rows 0..511 of w_qkv) -> fp16
    wgemm<true, 3, false><<<dim3(CC / 128, CC / 128, BB), 128, WG_SMEM>>>(
        mh, wqh, nullptr, mwh, nullptr, nullptr,
        CC, sCtx, 0, sCtx, CC, CC, CC);

    // 5) y = MW @ x + b_out (NN, fp32 + bias)
    wgemm<true, 0, true><<<dim3(LL / 128, CC / 128, BB), 128, WG_SMEM>>>(
        mwh, xh, y, nullptr, nullptr, b_out,
        CC, sCtx, sBig, sBig, CC, LL, LL);

    (void)out_size;
}

// round 17
// speedup vs baseline: 1.5125x; 1.5125x over previous
#include <cuda_runtime.h>
#include <cuda_fp16.h>
#include <cstdint>

// Problem shape (fixed)
#define BB 16
#define CC 512
#define LL 4096

typedef __half hf;

// ---------------- Scratch (device globals; no allocation allowed) -----------
__device__ __align__(256) hf g_xh[(size_t)BB * CC * LL];
__device__ __align__(256) hf g_vh[(size_t)BB * CC * LL];
__device__ __align__(256) hf g_kh[(size_t)BB * CC * LL];   // logits, then softmax in-place
__device__ __align__(256) hf g_ch[(size_t)BB * CC * CC];
__device__ __align__(256) hf g_mh[(size_t)BB * CC * CC];
__device__ __align__(256) hf g_mwh[(size_t)BB * CC * CC];  // MW = M @ Wq
__device__ __align__(256) hf g_wqh[3 * CC * CC];
__device__ __align__(256) hf g_woh[CC * CC];

// ---------------- PTX helpers ----------------
__device__ __forceinline__ uint32_t smem_u32(const void* p) {
    uint32_t a;
    asm("{ .reg .u64 t; cvta.to.shared.u64 t, %1; cvt.u32.u64 %0, t; }" : "=r"(a) : "l"(p));
    return a;
}
#define LDSM4(r0, r1, r2, r3, addr) \
    asm volatile("ldmatrix.sync.aligned.m8n8.x4.shared.b16 {%0,%1,%2,%3}, [%4];" \
                 : "=r"(r0), "=r"(r1), "=r"(r2), "=r"(r3) : "r"(addr))
#define LDSM4T(r0, r1, r2, r3, addr) \
    asm volatile("ldmatrix.sync.aligned.m8n8.x4.trans.shared.b16 {%0,%1,%2,%3}, [%4];" \
                 : "=r"(r0), "=r"(r1), "=r"(r2), "=r"(r3) : "r"(addr))
#define MMA16816(c, a, b) \
    asm volatile("mma.sync.aligned.m16n8k16.row.col.f32.f16.f16.f32 " \
                 "{%0,%1,%2,%3}, {%4,%5,%6,%7}, {%8,%9}, {%0,%1,%2,%3};" \
                 : "+f"((c)[0]), "+f"((c)[1]), "+f"((c)[2]), "+f"((c)[3]) \
                 : "r"((a)[0]), "r"((a)[1]), "r"((a)[2]), "r"((a)[3]), \
                   "r"((b)[0]), "r"((b)[1]))
#define CP16(dst, src) \
    asm volatile("cp.async.cg.shared.global [%0], [%1], 16;" :: "r"(dst), "l"(src))
#define CP_COMMIT() asm volatile("cp.async.commit_group;" ::: "memory")
#define CP_WAIT(n)  asm volatile("cp.async.wait_group %0;" :: "n"(n) : "memory")

__device__ __forceinline__ uint32_t pack2h(float f0, float f1) {
    __half2 h = __float22half2_rn(make_float2(f0, f1));
    return *reinterpret_cast<uint32_t*>(&h);
}

// ============================================================================
// wgemm: C[m,n] = sum_k A[m,k] * B'[k,n], fp16 1-pass HMMA.
//   B_IS_KN=true : B stored [K,N] (NN);  false: [N,K] (NT)
//   EPI: 0 = fp32 out (+bias), 2 = GEMM1 2-way fp16 (half 0->C0 k-logits,
//        half 1->C1 v), 3 = fp16 out (C0).
// Block tile 128x128, K-chunk 64, 3-stage cp.async ring (32KB stages),
// 128 thr (4 warps 2x2, warp tile 64x64), 2 CTAs/SM.
// ============================================================================
#define NSTAGE 3
#define STG_B  32768
#define WG_SMEM (NSTAGE * STG_B)   // 96 KB
#define P_BH 16384

template <bool B_IS_KN, int EPI, bool ADD_BIAS>
__global__ __launch_bounds__(128, 2) void wgemm(
    const hf* __restrict__ Ah, const hf* __restrict__ Bh,
    float* __restrict__ Cf, hf* __restrict__ C0, hf* __restrict__ C1,
    const float* __restrict__ bias,
    int K, long sA, long sB, long sC, int lda, int ldb, int ldc)
{
    extern __shared__ char smem[];
    const uint32_t sb = smem_u32(smem);

    const int tid  = threadIdx.x;
    const int lane = tid & 31;
    const int wid  = tid >> 5;          // 0..3
    const int wm   = wid >> 1;          // 0..1
    const int wn   = wid & 1;           // 0..1
    const int m0 = blockIdx.y * 128;
    const int n0 = blockIdx.x * 128;
    const long z = blockIdx.z;

    Ah += z * sA + (long)m0 * lda;
    Bh += z * sB + (B_IS_KN ? (long)n0 : (long)n0 * ldb);
    if (EPI == 0) Cf += z * sC;
    if (EPI == 2) { C0 += z * sC; C1 += z * sC; }
    if (EPI == 3) C0 += z * sC;

    const int ln15 = lane & 15;
    const int grp  = lane >> 4;
    const int sw8  = ln15 & 7;          // 128B-row swizzle key (per-lane)

    float acc[4][8][4];
    #pragma unroll
    for (int i = 0; i < 4; i++)
        #pragma unroll
        for (int j = 0; j < 8; j++)
            #pragma unroll
            for (int q = 0; q < 4; q++) acc[i][j][q] = 0.0f;

    // -------- cp.async stage fill (K-chunk 64) --------
    auto issue = [&](int chunk, int s) {
        const int k0 = chunk * 64;
        const uint32_t st = sb + s * STG_B;
        #pragma unroll
        for (int i = 0; i < 8; i++) {
            const int seg = tid + i * 128;
            const int row = seg >> 3;
            const int c   = seg & 7;
            const uint32_t doff = row * 128 + (((c ^ (row & 7)) & 7) << 4);
            CP16(st + doff, Ah + (long)row * lda + k0 + c * 8);
        }
        if (!B_IS_KN) {
            #pragma unroll
            for (int i = 0; i < 8; i++) {
                const int seg = tid + i * 128;
                const int row = seg >> 3;
                const int c   = seg & 7;
                const uint32_t doff = row * 128 + (((c ^ (row & 7)) & 7) << 4);
                CP16(st + P_BH + doff, Bh + (long)row * ldb + k0 + c * 8);
            }
        } else {
            // B plane: 64 k-rows x 256B, swizzle cc ^ (k&7)
            #pragma unroll
            for (int i = 0; i < 8; i++) {
                const int seg = tid + i * 128;
                const int k   = seg >> 4;
                const int cc  = seg & 15;
                const uint32_t doff = k * 256 + (((cc ^ (k & 7)) & 15) << 4);
                CP16(st + P_BH + doff, Bh + (long)(k0 + k) * ldb + cc * 8);
            }
        }
    };

    // -------- fragment loads --------
    int a_row_off[4];
    #pragma unroll
    for (int i = 0; i < 4; i++)
        a_row_off[i] = (wm * 64 + i * 16 + ln15) * 128;
    int b_row_off[4];
    #pragma unroll
    for (int jp = 0; jp < 4; jp++)
        b_row_off[jp] = (wn * 64 + jp * 16 + ln15) * 128;

    auto lda_frags = [&](uint32_t plane, int ks, uint32_t af[4][4]) {
        const int c = ks * 2 + grp;     // 0..7
        #pragma unroll
        for (int i = 0; i < 4; i++) {
            uint32_t addr = plane + a_row_off[i] + (((c ^ sw8) & 7) << 4);
            LDSM4(af[i][0], af[i][1], af[i][2], af[i][3], addr);
        }
    };
    auto ldb_frags = [&](uint32_t plane, int ks, uint32_t bf[8][2]) {
        if (B_IS_KN) {
            const uint32_t krow = (uint32_t)(ks * 16 + ln15) << 8;
            #pragma unroll
            for (int jp = 0; jp < 4; jp++) {
                const int cn = wn * 8 + jp * 2 + grp;
                uint32_t addr = plane + krow + (((cn ^ sw8) & 15) << 4);
                uint32_t r0, r1, r2, r3;
                LDSM4T(r0, r1, r2, r3, addr);
                bf[jp * 2    ][0] = r0; bf[jp * 2    ][1] = r1;
                bf[jp * 2 + 1][0] = r2; bf[jp * 2 + 1][1] = r3;
            }
        } else {
            const int c = ks * 2 + grp;
            #pragma unroll
            for (int jp = 0; jp < 4; jp++) {
                uint32_t addr = plane + b_row_off[jp] + (((c ^ sw8) & 7) << 4);
                uint32_t r0, r1, r2, r3;
                LDSM4(r0, r1, r2, r3, addr);
                bf[jp * 2    ][0] = r0; bf[jp * 2    ][1] = r2;
                bf[jp * 2 + 1][0] = r1; bf[jp * 2 + 1][1] = r3;
            }
        }
    };
    auto compute_chunk = [&](int s) {
        const uint32_t base = sb + s * STG_B;
        #pragma unroll
        for (int ks = 0; ks < 4; ks++) {
            uint32_t ah[4][4], bh[8][2];
            lda_frags(base, ks, ah);
            ldb_frags(base + P_BH, ks, bh);
            #pragma unroll
            for (int i = 0; i < 4; i++)
                #pragma unroll
                for (int j = 0; j < 8; j++)
                    MMA16816(acc[i][j], ah[i], bh[j]);
        }
    };

    // -------- multistage main loop (3-stage ring, mod-3 indexing) --------
    const int NC = K >> 6;
    issue(0, 0); CP_COMMIT();
    if (1 < NC) { issue(1, 1); } CP_COMMIT();
    int cur = 0, pfs = 2;
    for (int c = 0; c < NC; c++) {
        CP_WAIT(1);
        __syncthreads();
        const int pf = c + 2;
        if (pf < NC) { issue(pf, pfs); }
        CP_COMMIT();
        compute_chunk(cur);
        if (++cur == NSTAGE) cur = 0;
        if (++pfs == NSTAGE) pfs = 0;
    }

    // -------- epilogue --------
    #pragma unroll
    for (int i = 0; i < 4; i++) {
        const int row = m0 + wm * 64 + i * 16 + (lane >> 2);
        #pragma unroll
        for (int j = 0; j < 8; j++) {
            const int col = n0 + wn * 64 + j * 8 + (lane & 3) * 2;
            if (EPI == 0) {
                float bv0 = 0.0f, bv1 = 0.0f;
                if (ADD_BIAS) { bv0 = bias[row]; bv1 = bias[row + 8]; }
                float2 v0 = make_float2(acc[i][j][0] + bv0, acc[i][j][1] + bv0);
                float2 v1 = make_float2(acc[i][j][2] + bv1, acc[i][j][3] + bv1);
                *reinterpret_cast<float2*>(&Cf[(long)row * ldc + col])       = v0;
                *reinterpret_cast<float2*>(&Cf[(long)(row + 8) * ldc + col]) = v1;
            } else if (EPI == 3) {
                *reinterpret_cast<uint32_t*>(&C0[(long)row * ldc + col]) =
                    pack2h(acc[i][j][0], acc[i][j][1]);
                *reinterpret_cast<uint32_t*>(&C0[(long)(row + 8) * ldc + col]) =
                    pack2h(acc[i][j][2], acc[i][j][3]);
            } else {
                const int half = blockIdx.y >> 2;   // 4 m-tiles of 128 per 512 rows
                const int lr = row & 511;
                hf* d = (half == 0) ? C0 : C1;
                *reinterpret_cast<uint32_t*>(&d[(long)lr * ldc + col]) =
                    pack2h(acc[i][j][0], acc[i][j][1]);
                *reinterpret_cast<uint32_t*>(&d[(long)(lr + 8) * ldc + col]) =
                    pack2h(acc[i][j][2], acc[i][j][3]);
            }
        }
    }
}

// ============================================================================
// split kernel: fp32 -> half (8 elems/thread)
// ============================================================================
__global__ __launch_bounds__(256) void split_hi(
    const float* __restrict__ s, hf* __restrict__ h, long n)
{
    long i = ((long)blockIdx.x * 256 + threadIdx.x) * 8;
    if (i >= n) return;
    float4 v0 = *reinterpret_cast<const float4*>(s + i);
    float4 v1 = *reinterpret_cast<const float4*>(s + i + 4);
    uint4 o;
    o.x = pack2h(v0.x, v0.y); o.y = pack2h(v0.z, v0.w);
    o.z = pack2h(v1.x, v1.y); o.w = pack2h(v1.z, v1.w);
    *reinterpret_cast<uint4*>(h + i) = o;
}

// ============================================================================
// softmax over L, in-place on fp16 logits (block owns one full row)
// ============================================================================
__global__ __launch_bounds__(256) void softmax_h(hf* __restrict__ kh)
{
    const int r = blockIdx.x;
    const int b = blockIdx.y;
    const long off = ((long)b * CC + r) * LL;
    hf* p = kh + off;
    const int tid = threadIdx.x;
    __shared__ float red[8];

    float v[16];
    float mx = -1e30f;
    #pragma unroll
    for (int i = 0; i < 16; i++) { v[i] = __half2float(p[tid + i * 256]); mx = fmaxf(mx, v[i]); }
    #pragma unroll
    for (int o = 16; o > 0; o >>= 1) mx = fmaxf(mx, __shfl_xor_sync(0xffffffffu, mx, o));
    if ((tid & 31) == 0) red[tid >> 5] = mx;
    __syncthreads();
    if (tid < 32) {
        float m2 = (tid < 8) ? red[tid] : -1e30f;
        #pragma unroll
        for (int o = 4; o > 0; o >>= 1) m2 = fmaxf(m2, __shfl_xor_sync(0xffffffffu, m2, o));
        if (tid == 0) red[0] = m2;
    }
    __syncthreads();
    mx = red[0];
    __syncthreads();

    float s = 0.0f;
    #pragma unroll
    for (int i = 0; i < 16; i++) { v[i] = __expf(v[i] - mx); s += v[i]; }
    #pragma unroll
    for (int o = 16; o > 0; o >>= 1) s += __shfl_xor_sync(0xffffffffu, s, o);
    if ((tid & 31) == 0) red[tid >> 5] = s;
    __syncthreads();
    if (tid < 32) {
        float s2 = (tid < 8) ? red[tid] : 0.0f;
        #pragma unroll
        for (int o = 4; o > 0; o >>= 1) s2 += __shfl_xor_sync(0xffffffffu, s2, o);
        if (tid == 0) red[0] = s2;
    }
    __syncthreads();
    const float inv = 1.0f / red[0];

    #pragma unroll
    for (int i = 0; i < 16; i++)
        p[tid + i * 256] = __float2half_rn(v[i] * inv);
}

// ============================================================================
extern "C" void kernel_launch(void* const* d_in, const int* in_sizes, int n_in,
                              void* d_out, int out_size)
{
    const float* x = nullptr; const float* w_qkv = nullptr;
    const float* w_out = nullptr; const float* b_out = nullptr;
    for (int i = 0; i < n_in; i++) {
        switch (in_sizes[i]) {
            case 33554432: x     = (const float*)d_in[i]; break;
            case 786432:   w_qkv = (const float*)d_in[i]; break;
            case 262144:   w_out = (const float*)d_in[i]; break;
            case 512:      b_out = (const float*)d_in[i]; break;
            default: break;
        }
    }
    float* y = (float*)d_out;

    hf *xh, *vh, *kh, *ch, *mh, *mwh, *wqh, *woh;
    cudaGetSymbolAddress((void**)&xh, g_xh);
    cudaGetSymbolAddress((void**)&vh, g_vh);
    cudaGetSymbolAddress((void**)&kh, g_kh);
    cudaGetSymbolAddress((void**)&ch, g_ch);
    cudaGetSymbolAddress((void**)&mh, g_mh);
    cudaGetSymbolAddress((void**)&mwh, g_mwh);
    cudaGetSymbolAddress((void**)&wqh, g_wqh);
    cudaGetSymbolAddress((void**)&woh, g_woh);

    cudaFuncSetAttribute(wgemm<true,  2, false>, cudaFuncAttributeMaxDynamicSharedMemorySize, WG_SMEM);
    cudaFuncSetAttribute(wgemm<false, 3, false>, cudaFuncAttributeMaxDynamicSharedMemorySize, WG_SMEM);
    cudaFuncSetAttribute(wgemm<true,  3, false>, cudaFuncAttributeMaxDynamicSharedMemorySize, WG_SMEM);
    cudaFuncSetAttribute(wgemm<true,  0, true >, cudaFuncAttributeMaxDynamicSharedMemorySize, WG_SMEM);

    const long sBig = (long)CC * LL;
    const long sCtx = (long)CC * CC;

    // 0) pre-split inputs to fp16
    split_hi<<<(unsigned)((size_t)BB * CC * LL / 2048), 256>>>(x, xh, (long)BB * CC * LL);
    split_hi<<<3 * CC * CC / 2048, 256>>>(w_qkv, wqh, 3 * CC * CC);
    split_hi<<<CC * CC / 2048, 256>>>(w_out, woh, CC * CC);

    // 1) [k;v] = w_qkv[512:1536] @ x (NN): k-logits -> kh, v -> vh
    wgemm<true, 2, false><<<dim3(LL / 128, (2 * CC) / 128, BB), 128, WG_SMEM>>>(
        wqh + (long)CC * CC, xh, nullptr, kh, vh, nullptr,
        CC, 0, sBig, sBig, CC, LL, LL);

    // 2) softmax over L, in-place on kh
    softmax_h<<<dim3(CC, BB), 256>>>(kh);

    // 3) ctx = k_sm @ v^T (NT) -> fp16
    wgemm<false, 3, false><<<dim3(CC / 128, CC / 128, BB), 128, WG_SMEM>>>(
        kh, vh, nullptr, ch, nullptr, nullptr,
        LL, sBig, sBig, sCtx, LL, LL, CC);

    // 4) M = w_out @ ctx^T (NT) -> fp16
    wgemm<false, 3, false><<<dim3(CC / 128, CC / 128, BB), 128, WG_SMEM>>>(
        woh, ch, nullptr, mh, nullptr, nullptr,
        CC, 0, sCtx, sCtx, CC, CC, CC);

    // 4b) MW = M @ Wq (NN, Wq = rows 0..511 of w_qkv) -> fp16
    wgemm<true, 3, false><<<dim3(CC / 128, CC / 128, BB), 128, WG_SMEM>>>(
        mh, wqh, nullptr, mwh, nullptr, nullptr,
        CC, sCtx, 0, sCtx, CC, CC, CC);

    // 5) y = MW @ x + b_out (NN, fp32 + bias)
    wgemm<true, 0, true><<<dim3(LL / 128, CC / 128, BB), 128, WG_SMEM>>>(
        mwh, xh, y, nullptr, nullptr, b_out,
        CC, sCtx, sBig, sBig, CC, LL, LL);

    (void)out_size;
}